// round 16
// baseline (speedup 1.0000x reference)
#include <cuda_runtime.h>

#define N 4096
#define NN (N * N)
#define NITERS 300
#define NBLK 148
#define TPB 1024

__device__ unsigned short d_Kh[NN];   // K  = bf16(2^(-k*C)), 32MB, row-major
__device__ unsigned short d_KhT[NN];  // K^T, 32MB (coalesced g-pass)
__device__ float  d_F[N];             // potentials, log2 domain
__device__ float  d_G[N];
__device__ double d_csum;
__device__ double d_emd;
__device__ float  d_k;                // log2(e)/eps
__device__ unsigned int g_epoch;
__device__ unsigned int d_arr[NBLK];  // per-block arrival flags

__device__ __forceinline__ float  ldcg(const float* p)   { return __ldcg(p); }
__device__ __forceinline__ uint4  ldcg4(const uint4* p)  { return __ldcg(p); }
__device__ __forceinline__ float  bfl(unsigned u) { return __uint_as_float(u << 16); }
__device__ __forceinline__ float  bfh(unsigned u) { return __uint_as_float(u & 0xFFFF0000u); }

// ---------------------------------------------------------------- init
__global__ void k_init() {
    d_csum  = 0.0;
    d_emd   = 0.0;
    g_epoch = 0u;
    for (int i = 0; i < NBLK; i++) d_arr[i] = 0u;
}

// ---------------------------------------------------------------- csum; zero F/G
__global__ void k_sum(const float* __restrict__ x, const float* __restrict__ y) {
    __shared__ float sred[8];
    int i = blockIdx.x;
    float x0 = x[3 * i], x1 = x[3 * i + 1], x2 = x[3 * i + 2];
    float xx = x0 * x0 + x1 * x1 + x2 * x2;
    float acc = 0.0f;
    for (int j = threadIdx.x; j < N; j += 256) {
        float y0 = y[3 * j], y1 = y[3 * j + 1], y2 = y[3 * j + 2];
        float yy  = y0 * y0 + y1 * y1 + y2 * y2;
        float dot = x0 * y0 + x1 * y1 + x2 * y2;
        float d2  = xx + yy - 2.0f * dot;
        acc += sqrtf(fmaxf(d2, 0.0f) + 1e-12f);
    }
    for (int o = 16; o; o >>= 1) acc += __shfl_down_sync(0xffffffffu, acc, o);
    if ((threadIdx.x & 31) == 0) sred[threadIdx.x >> 5] = acc;
    __syncthreads();
    if (threadIdx.x < 8) {
        acc = sred[threadIdx.x];
        for (int o = 4; o; o >>= 1) acc += __shfl_down_sync(0xffu, acc, o);
        if (threadIdx.x == 0) atomicAdd(&d_csum, (double)acc);
    }
    if (threadIdx.x == 0) { d_F[i] = 0.0f; d_G[i] = 0.0f; }
}

// ---------------------------------------------------------------- eps -> k
__global__ void k_eps() {
    double mean = d_csum / ((double)N * (double)N);
    d_k = (float)(1.4426950408889634 / (0.02 * mean));
}

// ---------------------------------------------------------------- build (dst selected in device code!)
__global__ void k_buildK(int which,
                         const float* __restrict__ x, const float* __restrict__ y) {
    unsigned short* dst = which ? d_KhT : d_Kh;
    int i = blockIdx.x;
    float k = d_k;
    float x0 = x[3 * i], x1 = x[3 * i + 1], x2 = x[3 * i + 2];
    float xx = x0 * x0 + x1 * x1 + x2 * x2;
    for (int j = threadIdx.x; j < N; j += 256) {
        float y0 = y[3 * j], y1 = y[3 * j + 1], y2 = y[3 * j + 2];
        float yy  = y0 * y0 + y1 * y1 + y2 * y2;
        float dot = x0 * y0 + x1 * y1 + x2 * y2;
        float d2  = xx + yy - 2.0f * dot;
        float c   = sqrtf(fmaxf(d2, 0.0f) + 1e-12f);
        unsigned u = __float_as_uint(exp2f(-k * c));
        unsigned r = (u + 0x7FFFu + ((u >> 16) & 1u)) >> 16;   // rne bf16
        dst[(size_t)i * N + j] = (unsigned short)r;
    }
}

// ---------------------------------------------------------------- grid barrier: parallel flag arrival + single aggregator
__device__ __forceinline__ void gsync(unsigned int& ep, int tid, int bid) {
    __syncthreads();
    ep++;
    if (bid == 0) {
        if (tid < 32) {
            if (tid == 0)
                asm volatile("st.release.gpu.u32 [%0], %1;" :: "l"(&d_arr[0]), "r"(ep) : "memory");
            bool done;
            do {
                done = true;
                for (int f = tid; f < NBLK; f += 32) {
                    unsigned v;
                    asm volatile("ld.acquire.gpu.u32 %0, [%1];" : "=r"(v) : "l"(&d_arr[f]) : "memory");
                    done &= (v >= ep);
                }
            } while (!__all_sync(0xffffffffu, done));
            if (tid == 0)
                asm volatile("st.release.gpu.u32 [%0], %1;" :: "l"(&g_epoch), "r"(ep) : "memory");
        }
    } else {
        if (tid == 0) {
            asm volatile("st.release.gpu.u32 [%0], %1;" :: "l"(&d_arr[bid]), "r"(ep) : "memory");
            unsigned v;
            do {
                asm volatile("ld.acquire.gpu.u32 %0, [%1];" : "=r"(v) : "l"(&g_epoch) : "memory");
            } while (v < ep);
        }
    }
    __syncthreads();
}

// ---------------------------------------------------------------- stage src into split smem (conflict-free reads), return global max
// layout: element j (q=j>>3, r=j&7): r<4 -> sVa[q*4+r], else sVb[q*4+r-4]
__device__ __forceinline__ float blockmax_stage(const float* __restrict__ src,
                                                float* sVa, float* sVb,
                                                float* sred, float* sMax,
                                                int tid, int wid, int ln) {
    float vals[N / TPB];
    float m = -1e30f;
#pragma unroll
    for (int s = 0; s < N / TPB; s++) {
        float v = __ldcg(&src[tid + s * TPB]);
        vals[s] = v;
        m = fmaxf(m, v);
    }
    for (int o = 16; o; o >>= 1) m = fmaxf(m, __shfl_xor_sync(0xffffffffu, m, o));
    if (ln == 0) sred[wid] = m;
    __syncthreads();
    if (tid < 32) {
        float t = sred[tid];
        for (int o = 16; o; o >>= 1) t = fmaxf(t, __shfl_xor_sync(0xffffffffu, t, o));
        if (tid == 0) *sMax = t;
    }
    __syncthreads();
    float h = *sMax;
#pragma unroll
    for (int s = 0; s < N / TPB; s++) {
        int j = tid + s * TPB;
        float e = exp2f(vals[s] - h);
        int q = j >> 3, r = j & 7;
        if (r < 4) sVa[q * 4 + r] = e;
        else       sVb[q * 4 + (r - 4)] = e;
    }
    __syncthreads();
    return h;
}

// ---------------------------------------------------------------- persistent Sinkhorn + final P*C
__global__ void __launch_bounds__(TPB, 1) k_persist(float* __restrict__ out) {
    __shared__ float sVst[N + 16];       // split V: sVa[2048], pad 16, sVb[2048]
    __shared__ float sred[32];
    __shared__ float sMax;
    float* sVa = sVst;
    float* sVb = sVst + N / 2 + 16;
    const int tid = threadIdx.x;
    const int bid = blockIdx.x;
    const int wid = tid >> 5;
    const int ln  = tid & 31;
    const int frow = bid + NBLK * wid;   // round-robin row/col; valid if < N
    unsigned int ep = 0u;

    for (int it = 0; it < NITERS; it++) {
        // ==== f pass: S_i = sum_j K_ij 2^(G_j-Gh);  F_i = 12 - Gh - log2(S_i)
        {
            const float Gh = blockmax_stage(d_G, sVa, sVb, sred, &sMax, tid, wid, ln);
            if (frow < N) {
                const uint4*  Kr = (const uint4*)(d_Kh + (size_t)frow * N);
                const float4* Va = (const float4*)sVa;
                const float4* Vb = (const float4*)sVb;
                float s0 = 0.f, s1 = 0.f, s2 = 0.f, s3 = 0.f;
#pragma unroll 4
                for (int t = ln; t < N / 8; t += 32) {
                    uint4  q  = ldcg4(&Kr[t]);
                    float4 va = Va[t];                  // conflict-free: 16B/lane consecutive
                    float4 vb = Vb[t];
                    s0 = fmaf(bfl(q.x), va.x, s0);
                    s1 = fmaf(bfh(q.x), va.y, s1);
                    s2 = fmaf(bfl(q.y), va.z, s2);
                    s3 = fmaf(bfh(q.y), va.w, s3);
                    s0 = fmaf(bfl(q.z), vb.x, s0);
                    s1 = fmaf(bfh(q.z), vb.y, s1);
                    s2 = fmaf(bfl(q.w), vb.z, s2);
                    s3 = fmaf(bfh(q.w), vb.w, s3);
                }
                float s = (s0 + s1) + (s2 + s3);
                for (int o = 16; o; o >>= 1) s += __shfl_down_sync(0xffffffffu, s, o);
                if (ln == 0) d_F[frow] = 12.0f - Gh - log2f(fmaxf(s, 1e-38f));
            }
        }
        gsync(ep, tid, bid);

        // ==== g pass: T_j = sum_i K^T_ji 2^(F_i-Fh);  G_j = 12 - Fh - log2(T_j)
        {
            const float Fh = blockmax_stage(d_F, sVa, sVb, sred, &sMax, tid, wid, ln);
            if (frow < N) {
                const uint4*  Kr = (const uint4*)(d_KhT + (size_t)frow * N);
                const float4* Va = (const float4*)sVa;
                const float4* Vb = (const float4*)sVb;
                float s0 = 0.f, s1 = 0.f, s2 = 0.f, s3 = 0.f;
#pragma unroll 4
                for (int t = ln; t < N / 8; t += 32) {
                    uint4  q  = ldcg4(&Kr[t]);
                    float4 va = Va[t];
                    float4 vb = Vb[t];
                    s0 = fmaf(bfl(q.x), va.x, s0);
                    s1 = fmaf(bfh(q.x), va.y, s1);
                    s2 = fmaf(bfl(q.y), va.z, s2);
                    s3 = fmaf(bfh(q.y), va.w, s3);
                    s0 = fmaf(bfl(q.z), vb.x, s0);
                    s1 = fmaf(bfh(q.z), vb.y, s1);
                    s2 = fmaf(bfl(q.w), vb.z, s2);
                    s3 = fmaf(bfh(q.w), vb.w, s3);
                }
                float s = (s0 + s1) + (s2 + s3);
                for (int o = 16; o; o >>= 1) s += __shfl_down_sync(0xffffffffu, s, o);
                if (ln == 0) d_G[frow] = 12.0f - Fh - log2f(fmaxf(s, 1e-38f));
            }
        }
        gsync(ep, tid, bid);
    }

    // ==== final: EMD = sum P*C,  P = U V K 2^(Fh+Gh-24),  C = -log2(K)/k
    {
        const float Gh = blockmax_stage(d_G, sVa, sVb, sred, &sMax, tid, wid, ln);
        float m = -1e30f;
        for (int i = tid; i < N; i += TPB) m = fmaxf(m, ldcg(&d_F[i]));
        for (int o = 16; o; o >>= 1) m = fmaxf(m, __shfl_xor_sync(0xffffffffu, m, o));
        if (ln == 0) sred[wid] = m;
        __syncthreads();
        if (tid < 32) {
            float t = sred[tid];
            for (int o = 16; o; o >>= 1) t = fmaxf(t, __shfl_xor_sync(0xffffffffu, t, o));
            if (tid == 0) sMax = t;
        }
        __syncthreads();
        const float Fh = sMax;

        float s = 0.f;
        if (frow < N) {
            const float U = exp2f(ldcg(&d_F[frow]) - Fh);
            const uint4*  Kr = (const uint4*)(d_Kh + (size_t)frow * N);
            const float4* Va = (const float4*)sVa;
            const float4* Vb = (const float4*)sVb;
            float a0 = 0.f, a1 = 0.f, a2 = 0.f, a3 = 0.f;
#pragma unroll 2
            for (int t = ln; t < N / 8; t += 32) {
                uint4  q  = ldcg4(&Kr[t]);
                float4 va = Va[t];
                float4 vb = Vb[t];
                float b0 = bfl(q.x), b1 = bfh(q.x), b2 = bfl(q.y), b3 = bfh(q.y);
                float b4 = bfl(q.z), b5 = bfh(q.z), b6 = bfl(q.w), b7 = bfh(q.w);
                a0 += (b0 > 1e-30f) ? -b0 * va.x * __log2f(b0) : 0.f;
                a1 += (b1 > 1e-30f) ? -b1 * va.y * __log2f(b1) : 0.f;
                a2 += (b2 > 1e-30f) ? -b2 * va.z * __log2f(b2) : 0.f;
                a3 += (b3 > 1e-30f) ? -b3 * va.w * __log2f(b3) : 0.f;
                a0 += (b4 > 1e-30f) ? -b4 * vb.x * __log2f(b4) : 0.f;
                a1 += (b5 > 1e-30f) ? -b5 * vb.y * __log2f(b5) : 0.f;
                a2 += (b6 > 1e-30f) ? -b6 * vb.z * __log2f(b6) : 0.f;
                a3 += (b7 > 1e-30f) ? -b7 * vb.w * __log2f(b7) : 0.f;
            }
            s = U * ((a0 + a1) + (a2 + a3));
            for (int o = 16; o; o >>= 1) s += __shfl_down_sync(0xffffffffu, s, o);
        }
        if (ln == 0) sred[wid] = s;
        __syncthreads();
        if (tid < 32) {
            s = sred[tid];
            for (int o = 16; o; o >>= 1) s += __shfl_down_sync(0xffffffffu, s, o);
            if (tid == 0) atomicAdd(&d_emd, (double)s);
        }
        gsync(ep, tid, bid);
        if (bid == 0 && tid == 0) {
            double emd = __ldcg((const double*)&d_emd);
            out[0] = (float)(emd * exp2((double)Fh + (double)Gh - 24.0) / (double)d_k);
        }
    }
}

// ---------------------------------------------------------------- launch
extern "C" void kernel_launch(void* const* d_in, const int* in_sizes, int n_in,
                              void* d_out, int out_size) {
    const float* x = (const float*)d_in[0];
    const float* y = (const float*)d_in[1];
    float* out = (float*)d_out;

    k_init<<<1, 1>>>();
    k_sum<<<N, 256>>>(x, y);
    k_eps<<<1, 1>>>();
    k_buildK<<<N, 256>>>(0, x, y);   // d_Kh  : rows = x
    k_buildK<<<N, 256>>>(1, y, x);   // d_KhT : rows = y (transpose)
    k_persist<<<NBLK, TPB>>>(out);
}

// round 17
// speedup vs baseline: 1.2118x; 1.2118x over previous
#include <cuda_runtime.h>

#define N 4096
#define NN (N * N)
#define NITERS 300
#define NBLK 148
#define TPB 1024
#define AMARG 0.000244140625f   // 1/4096 uniform marginal

__device__ unsigned short d_Kh[NN];   // K  = bf16(2^(-k*C)), 32MB, row-major
__device__ unsigned short d_KhT[NN];  // K^T, 32MB (coalesced g-pass)
__device__ float  d_U[N];             // scaling vectors (linear domain)
__device__ float  d_V[N];
__device__ double d_csum;
__device__ double d_emd;
__device__ float  d_k;                // log2(e)/eps
__device__ unsigned int g_bar;
__device__ unsigned int g_epoch;

__device__ __forceinline__ float  ldcg(const float* p)   { return __ldcg(p); }
__device__ __forceinline__ uint4  ldcg4(const uint4* p)  { return __ldcg(p); }
__device__ __forceinline__ float  bfl(unsigned u) { return __uint_as_float(u << 16); }
__device__ __forceinline__ float  bfh(unsigned u) { return __uint_as_float(u & 0xFFFF0000u); }

// ---------------------------------------------------------------- init
__global__ void k_init() {
    d_csum  = 0.0;
    d_emd   = 0.0;
    g_bar   = 0u;
    g_epoch = 0u;
}

// ---------------------------------------------------------------- v0 = b = 1/n
__global__ void k_vinit() {
    int i = blockIdx.x * 1024 + threadIdx.x;
    d_V[i] = AMARG;
    d_U[i] = AMARG;
}

// ---------------------------------------------------------------- csum
__global__ void k_sum(const float* __restrict__ x, const float* __restrict__ y) {
    __shared__ float sred[8];
    int i = blockIdx.x;
    float x0 = x[3 * i], x1 = x[3 * i + 1], x2 = x[3 * i + 2];
    float xx = x0 * x0 + x1 * x1 + x2 * x2;
    float acc = 0.0f;
    for (int j = threadIdx.x; j < N; j += 256) {
        float y0 = y[3 * j], y1 = y[3 * j + 1], y2 = y[3 * j + 2];
        float yy  = y0 * y0 + y1 * y1 + y2 * y2;
        float dot = x0 * y0 + x1 * y1 + x2 * y2;
        float d2  = xx + yy - 2.0f * dot;
        acc += sqrtf(fmaxf(d2, 0.0f) + 1e-12f);
    }
    for (int o = 16; o; o >>= 1) acc += __shfl_down_sync(0xffffffffu, acc, o);
    if ((threadIdx.x & 31) == 0) sred[threadIdx.x >> 5] = acc;
    __syncthreads();
    if (threadIdx.x < 8) {
        acc = sred[threadIdx.x];
        for (int o = 4; o; o >>= 1) acc += __shfl_down_sync(0xffu, acc, o);
        if (threadIdx.x == 0) atomicAdd(&d_csum, (double)acc);
    }
}

// ---------------------------------------------------------------- eps -> k
__global__ void k_eps() {
    double mean = d_csum / ((double)N * (double)N);
    d_k = (float)(1.4426950408889634 / (0.02 * mean));
}

// ---------------------------------------------------------------- build (dst selected in device code!)
__global__ void k_buildK(int which,
                         const float* __restrict__ x, const float* __restrict__ y) {
    unsigned short* dst = which ? d_KhT : d_Kh;
    int i = blockIdx.x;
    float k = d_k;
    float x0 = x[3 * i], x1 = x[3 * i + 1], x2 = x[3 * i + 2];
    float xx = x0 * x0 + x1 * x1 + x2 * x2;
    for (int j = threadIdx.x; j < N; j += 256) {
        float y0 = y[3 * j], y1 = y[3 * j + 1], y2 = y[3 * j + 2];
        float yy  = y0 * y0 + y1 * y1 + y2 * y2;
        float dot = x0 * y0 + x1 * y1 + x2 * y2;
        float d2  = xx + yy - 2.0f * dot;
        float c   = sqrtf(fmaxf(d2, 0.0f) + 1e-12f);
        unsigned u = __float_as_uint(exp2f(-k * c));
        unsigned r = (u + 0x7FFFu + ((u >> 16) & 1u)) >> 16;   // rne bf16
        dst[(size_t)i * N + j] = (unsigned short)r;
    }
}

// ---------------------------------------------------------------- grid barrier (R15-proven)
__device__ __forceinline__ void gsync(unsigned int& ep) {
    __syncthreads();
    if (threadIdx.x == 0) {
        unsigned int t;
        asm volatile("atom.add.release.gpu.u32 %0, [%1], 1;"
                     : "=r"(t) : "l"(&g_bar) : "memory");
        if (t == NBLK - 1) {
            g_bar = 0u;
            asm volatile("st.release.gpu.u32 [%0], %1;"
                         :: "l"(&g_epoch), "r"(ep + 1u) : "memory");
        } else {
            unsigned int v;
            do {
                asm volatile("ld.acquire.gpu.u32 %0, [%1];"
                             : "=r"(v) : "l"(&g_epoch) : "memory");
            } while (v == ep);
        }
    }
    ep++;
    __syncthreads();
}

// ---------------------------------------------------------------- one scaling sweep: W[row] = AMARG / sum_col(M[row,:] * Vec)
// Kmat: bf16 matrix (row-major), Vec: staged source, W: output vector
__device__ __forceinline__ void sweep(const unsigned short* __restrict__ Kmat,
                                      const float* __restrict__ Vec,
                                      float* __restrict__ W,
                                      float* sV, int tid, int wid, int ln, int frow) {
    // prefetch first 2 K chunks (constant data: overlaps staging latency)
    uint4 p0, p1;
    const uint4* Kr = (const uint4*)(Kmat + (size_t)frow * N);
    if (frow < N) { p0 = ldcg4(&Kr[ln]); p1 = ldcg4(&Kr[ln + 32]); }
    // stage Vec -> smem (pure copy, one float4 per thread)
    ((float4*)sV)[tid] = __ldcg(&((const float4*)Vec)[tid]);
    __syncthreads();
    if (frow < N) {
        const float4* V4 = (const float4*)sV;
        float s0 = 0.f, s1 = 0.f, s2 = 0.f, s3 = 0.f;
        // prefetched chunks: t = ln, ln+32
        {
            float4 va = V4[2 * ln],        vb = V4[2 * ln + 1];
            s0 = fmaf(bfl(p0.x), va.x, s0);
            s1 = fmaf(bfh(p0.x), va.y, s1);
            s2 = fmaf(bfl(p0.y), va.z, s2);
            s3 = fmaf(bfh(p0.y), va.w, s3);
            s0 = fmaf(bfl(p0.z), vb.x, s0);
            s1 = fmaf(bfh(p0.z), vb.y, s1);
            s2 = fmaf(bfl(p0.w), vb.z, s2);
            s3 = fmaf(bfh(p0.w), vb.w, s3);
            int t1 = ln + 32;
            float4 vc = V4[2 * t1],        vd = V4[2 * t1 + 1];
            s0 = fmaf(bfl(p1.x), vc.x, s0);
            s1 = fmaf(bfh(p1.x), vc.y, s1);
            s2 = fmaf(bfl(p1.y), vc.z, s2);
            s3 = fmaf(bfh(p1.y), vc.w, s3);
            s0 = fmaf(bfl(p1.z), vd.x, s0);
            s1 = fmaf(bfh(p1.z), vd.y, s1);
            s2 = fmaf(bfl(p1.w), vd.z, s2);
            s3 = fmaf(bfh(p1.w), vd.w, s3);
        }
#pragma unroll 4
        for (int t = ln + 64; t < N / 8; t += 32) {
            uint4  q  = ldcg4(&Kr[t]);
            float4 va = V4[2 * t];
            float4 vb = V4[2 * t + 1];
            s0 = fmaf(bfl(q.x), va.x, s0);
            s1 = fmaf(bfh(q.x), va.y, s1);
            s2 = fmaf(bfl(q.y), va.z, s2);
            s3 = fmaf(bfh(q.y), va.w, s3);
            s0 = fmaf(bfl(q.z), vb.x, s0);
            s1 = fmaf(bfh(q.z), vb.y, s1);
            s2 = fmaf(bfl(q.w), vb.z, s2);
            s3 = fmaf(bfh(q.w), vb.w, s3);
        }
        float s = (s0 + s1) + (s2 + s3);
        for (int o = 16; o; o >>= 1) s += __shfl_down_sync(0xffffffffu, s, o);
        if (ln == 0) W[frow] = AMARG / fmaxf(s, 1e-35f);
    }
}

// ---------------------------------------------------------------- persistent linear Sinkhorn + final P*C
__global__ void __launch_bounds__(TPB, 1) k_persist(float* __restrict__ out) {
    __shared__ float sV[N];
    __shared__ float sred[32];
    const int tid = threadIdx.x;
    const int bid = blockIdx.x;
    const int wid = tid >> 5;
    const int ln  = tid & 31;
    const int frow = bid + NBLK * wid;   // round-robin row/col; valid if < N
    unsigned int ep = 0u;

    for (int it = 0; it < NITERS; it++) {
        // f pass: u_i = a / sum_j K_ij v_j
        sweep(d_Kh, d_V, d_U, sV, tid, wid, ln, frow);
        gsync(ep);
        // g pass: v_j = b / sum_i K^T_ji u_i
        sweep(d_KhT, d_U, d_V, sV, tid, wid, ln, frow);
        gsync(ep);
    }

    // ==== final: EMD = sum_ij u_i K_ij v_j * C_ij,  C = -log2(K)/k
    {
        ((float4*)sV)[tid] = __ldcg(&((const float4*)d_V)[tid]);
        __syncthreads();
        float s = 0.f;
        if (frow < N) {
            const float U = ldcg(&d_U[frow]);
            const uint4*  Kr = (const uint4*)(d_Kh + (size_t)frow * N);
            const float4* V4 = (const float4*)sV;
            float a0 = 0.f, a1 = 0.f, a2 = 0.f, a3 = 0.f;
#pragma unroll 2
            for (int t = ln; t < N / 8; t += 32) {
                uint4  q  = ldcg4(&Kr[t]);
                float4 va = V4[2 * t];
                float4 vb = V4[2 * t + 1];
                float b0 = bfl(q.x), b1 = bfh(q.x), b2 = bfl(q.y), b3 = bfh(q.y);
                float b4 = bfl(q.z), b5 = bfh(q.z), b6 = bfl(q.w), b7 = bfh(q.w);
                a0 += (b0 > 1e-30f) ? -b0 * va.x * __log2f(b0) : 0.f;
                a1 += (b1 > 1e-30f) ? -b1 * va.y * __log2f(b1) : 0.f;
                a2 += (b2 > 1e-30f) ? -b2 * va.z * __log2f(b2) : 0.f;
                a3 += (b3 > 1e-30f) ? -b3 * va.w * __log2f(b3) : 0.f;
                a0 += (b4 > 1e-30f) ? -b4 * vb.x * __log2f(b4) : 0.f;
                a1 += (b5 > 1e-30f) ? -b5 * vb.y * __log2f(b5) : 0.f;
                a2 += (b6 > 1e-30f) ? -b6 * vb.z * __log2f(b6) : 0.f;
                a3 += (b7 > 1e-30f) ? -b7 * vb.w * __log2f(b7) : 0.f;
            }
            s = U * ((a0 + a1) + (a2 + a3));
            for (int o = 16; o; o >>= 1) s += __shfl_down_sync(0xffffffffu, s, o);
        }
        if (ln == 0) sred[wid] = s;
        __syncthreads();
        if (tid < 32) {
            s = sred[tid];
            for (int o = 16; o; o >>= 1) s += __shfl_down_sync(0xffffffffu, s, o);
            if (tid == 0) atomicAdd(&d_emd, (double)s);
        }
        gsync(ep);
        if (bid == 0 && tid == 0) {
            double emd = __ldcg((const double*)&d_emd);
            out[0] = (float)(emd / (double)d_k);
        }
    }
}

// ---------------------------------------------------------------- launch
extern "C" void kernel_launch(void* const* d_in, const int* in_sizes, int n_in,
                              void* d_out, int out_size) {
    const float* x = (const float*)d_in[0];
    const float* y = (const float*)d_in[1];
    float* out = (float*)d_out;

    k_init<<<1, 1>>>();
    k_vinit<<<N / 1024, 1024>>>();
    k_sum<<<N, 256>>>(x, y);
    k_eps<<<1, 1>>>();
    k_buildK<<<N, 256>>>(0, x, y);   // d_Kh  : rows = x
    k_buildK<<<N, 256>>>(1, y, x);   // d_KhT : rows = y (transpose)
    k_persist<<<NBLK, TPB>>>(out);
}